// round 9
// baseline (speedup 1.0000x reference)
#include <cuda_runtime.h>
#include <cstdint>

#define NUM_BUCKETS  16384
#define HIDDEN       768
#define LN_EPS       1e-6f
#define TOK          8        // tokens per warp

__global__ __launch_bounds__(256, 2)
void canine_emb_ln_kernel(const int* __restrict__ ids,
                          const float* __restrict__ tables,
                          const float* __restrict__ ln_scale,
                          const float* __restrict__ ln_bias,
                          float* __restrict__ out,
                          int n_tokens)
{
    const int warp = (blockIdx.x * blockDim.x + threadIdx.x) >> 5;
    const int lane = threadIdx.x & 31;

    // Per-k compile-time tables (folded to immediates after full unroll).
    // f = lane + 32k spans at most 2 hash tables: h0 = floor(32k/24),
    // lane threshold TT = 24*(h0+1) - 32k. primes = {31,43,59,61,73,97,103,113}.
    const int      H0[6] = {0, 1, 2, 4, 5, 6};
    const int      TT[6] = {24, 16, 8, 24, 16, 8};
    const unsigned P0[6] = {31u, 43u, 59u, 73u, 97u, 103u};
    const unsigned P1[6] = {43u, 59u, 61u, 97u, 103u, 113u};

    const float4* t4 = reinterpret_cast<const float4*>(tables);
    const float4* sc = reinterpret_cast<const float4*>(ln_scale);
    const float4* bi = reinterpret_cast<const float4*>(ln_bias);

    // Cache scale/bias in registers ONCE per warp (amortized over TOK tokens).
    float4 S[6], B[6];
#pragma unroll
    for (int k = 0; k < 6; k++) {
        S[k] = __ldg(sc + lane + 32 * k);
        B[k] = __ldg(bi + lane + 32 * k);
    }

    const int tok0 = warp * TOK;

    for (int t = 0; t < TOK; t++) {
        const int tok = tok0 + t;
        if (tok >= n_tokens) return;

        // ids are int32 (JAX downcasts the declared int64). Broadcast load.
        const unsigned int h32 = (unsigned int)(__ldg(ids + tok) + 1);

        // Single-pass gather: hold the 6 float4, accumulate moments.
        float4 vec[6];
        float sum = 0.f, sumsq = 0.f;
#pragma unroll
        for (int k = 0; k < 6; k++) {
            const int f = lane + 32 * k;
            const int hi = (lane >= TT[k]) ? 1 : 0;      // compile-time threshold
            const int h = H0[k] + hi;
            const unsigned prime  = hi ? P1[k] : P0[k];  // SEL of immediates
            const unsigned bucket = (h32 * prime) & (NUM_BUCKETS - 1);
            const int idx = ((h << 14) | (int)bucket) * 24 + (f - 24 * h);
            const float4 x = __ldg(t4 + idx);
            vec[k] = x;
            sum   += x.x + x.y + x.z + x.w;
            sumsq += x.x * x.x + x.y * x.y + x.z * x.z + x.w * x.w;
        }

        // Warp reduction of moments.
#pragma unroll
        for (int o = 16; o > 0; o >>= 1) {
            sum   += __shfl_xor_sync(0xffffffffu, sum,   o);
            sumsq += __shfl_xor_sync(0xffffffffu, sumsq, o);
        }
        const float inv_n = 1.0f / (float)HIDDEN;
        const float mean  = sum * inv_n;
        const float var   = fmaxf(sumsq * inv_n - mean * mean, 0.0f);
        const float rstd  = rsqrtf(var + LN_EPS);

        float4* op = reinterpret_cast<float4*>(out + (size_t)tok * HIDDEN);

#pragma unroll
        for (int k = 0; k < 6; k++) {
            const float4 x = vec[k];
            const float4 s = S[k];
            const float4 b = B[k];
            float4 r;
            r.x = fmaf((x.x - mean) * rstd, s.x, b.x);
            r.y = fmaf((x.y - mean) * rstd, s.y, b.y);
            r.z = fmaf((x.z - mean) * rstd, s.z, b.z);
            r.w = fmaf((x.w - mean) * rstd, s.w, b.w);
            // EXPERIMENT (one-variable change vs R8): plain evict-normal store
            // instead of __stcs. Theory T3: evict-first caused fine-grained
            // read/write interleave at DRAM (bus turnaround) capping HBM at
            // ~55%; letting L2 aggregate the write stream should raise DRAM
            // efficiency. Risk T4: output stream now evicts the table.
            op[lane + 32 * k] = r;
        }
    }
}

extern "C" void kernel_launch(void* const* d_in, const int* in_sizes, int n_in,
                              void* d_out, int out_size)
{
    const int*   ids      = (const int*)d_in[0];     // [8, 8192] int32
    const float* tables   = (const float*)d_in[1];   // [8, 16384, 96] f32
    const float* ln_scale = (const float*)d_in[2];   // [768]
    const float* ln_bias  = (const float*)d_in[3];   // [768]
    float*       out      = (float*)d_out;           // [8, 8192, 768] f32

    const int n_tokens = in_sizes[0];                // 65536
    const int n_warps  = (n_tokens + TOK - 1) / TOK; // 8192
    const int warps_per_block = 8;                   // 256 threads
    const int blocks = (n_warps + warps_per_block - 1) / warps_per_block;  // 1024
    canine_emb_ln_kernel<<<blocks, warps_per_block * 32>>>(
        ids, tables, ln_scale, ln_bias, out, n_tokens);
}

// round 10
// speedup vs baseline: 1.1657x; 1.1657x over previous
#include <cuda_runtime.h>
#include <cstdint>

#define NUM_BUCKETS  16384
#define HIDDEN       768
#define LN_EPS       1e-6f

__global__ __launch_bounds__(256, 5)
void canine_emb_ln_kernel(const int* __restrict__ ids,
                          const float* __restrict__ tables,
                          const float* __restrict__ ln_scale,
                          const float* __restrict__ ln_bias,
                          float* __restrict__ out,
                          int n_tokens)
{
    const int warp = (blockIdx.x * blockDim.x + threadIdx.x) >> 5;
    const int lane = threadIdx.x & 31;
    if (warp >= n_tokens) return;

    // ids are int32 (JAX downcasts the declared int64). Broadcast load.
    const unsigned int h32 = (unsigned int)(__ldg(ids + warp) + 1);

    // Per-k compile-time tables (folded to immediates after full unroll).
    // f = lane + 32k spans at most 2 hash tables: h0 = floor(32k/24),
    // lane threshold TT = 24*(h0+1) - 32k. primes = {31,43,59,61,73,97,103,113}.
    const int      H0[6] = {0, 1, 2, 4, 5, 6};
    const int      TT[6] = {24, 16, 8, 24, 16, 8};
    const unsigned P0[6] = {31u, 43u, 59u, 73u, 97u, 103u};
    const unsigned P1[6] = {43u, 59u, 61u, 97u, 103u, 113u};

    const float4* t4 = reinterpret_cast<const float4*>(tables);

    // Single-pass gather: front-batched 6 LDG.128, hold the vectors,
    // accumulate moments. (R4 structure — best measured — with the
    // immediate-prime hash replacing div/mod/LDC.)
    float4 vec[6];
    float sum = 0.f, sumsq = 0.f;
#pragma unroll
    for (int k = 0; k < 6; k++) {
        const int f = lane + 32 * k;
        const int hi = (lane >= TT[k]) ? 1 : 0;      // compile-time threshold
        const int h = H0[k] + hi;
        const unsigned prime  = hi ? P1[k] : P0[k];  // SEL of immediates
        const unsigned bucket = (h32 * prime) & (NUM_BUCKETS - 1);
        const int idx = ((h << 14) | (int)bucket) * 24 + (f - 24 * h);
        const float4 x = __ldg(t4 + idx);
        vec[k] = x;
        sum   += x.x + x.y + x.z + x.w;
        sumsq += x.x * x.x + x.y * x.y + x.z * x.z + x.w * x.w;
    }

    // Warp reduction of moments.
#pragma unroll
    for (int o = 16; o > 0; o >>= 1) {
        sum   += __shfl_xor_sync(0xffffffffu, sum,   o);
        sumsq += __shfl_xor_sync(0xffffffffu, sumsq, o);
    }
    const float inv_n = 1.0f / (float)HIDDEN;
    const float mean  = sum * inv_n;
    const float var   = fmaxf(sumsq * inv_n - mean * mean, 0.0f);
    const float rstd  = rsqrtf(var + LN_EPS);

    float4* op = reinterpret_cast<float4*>(out + (size_t)warp * HIDDEN);
    const float4* sc = reinterpret_cast<const float4*>(ln_scale);
    const float4* bi = reinterpret_cast<const float4*>(ln_bias);

#pragma unroll
    for (int k = 0; k < 6; k++) {
        const int f = lane + 32 * k;
        const float4 s = __ldg(sc + f);   // L1/L2-resident (768 floats total)
        const float4 b = __ldg(bi + f);
        const float4 x = vec[k];
        float4 r;
        r.x = fmaf((x.x - mean) * rstd, s.x, b.x);
        r.y = fmaf((x.y - mean) * rstd, s.y, b.y);
        r.z = fmaf((x.z - mean) * rstd, s.z, b.z);
        r.w = fmaf((x.w - mean) * rstd, s.w, b.w);
        // Streaming store (verified in R9: removing it costs ~3.5 µs):
        // protect the 50 MB L2-resident table from the 201 MB output stream.
        __stcs(op + f, r);
    }
}

extern "C" void kernel_launch(void* const* d_in, const int* in_sizes, int n_in,
                              void* d_out, int out_size)
{
    const int*   ids      = (const int*)d_in[0];     // [8, 8192] int32
    const float* tables   = (const float*)d_in[1];   // [8, 16384, 96] f32
    const float* ln_scale = (const float*)d_in[2];   // [768]
    const float* ln_bias  = (const float*)d_in[3];   // [768]
    float*       out      = (float*)d_out;           // [8, 8192, 768] f32

    const int n_tokens = in_sizes[0];                // 65536
    const int warps_per_block = 8;                   // 256 threads
    const int blocks = (n_tokens + warps_per_block - 1) / warps_per_block;  // 8192
    canine_emb_ln_kernel<<<blocks, warps_per_block * 32>>>(
        ids, tables, ln_scale, ln_bias, out, n_tokens);
}